// round 7
// baseline (speedup 1.0000x reference)
#include <cuda_runtime.h>
#include <math.h>

#define NB   16
#define CIN  256
#define MIP  64
#define SEQ  192

// ---- scratch (device globals; no allocation allowed) ----
__device__ float g_y0[NB * CIN * SEQ];    // pooled + concat (b, 256, 192)
__device__ float g_y2[NB * MIP * SEQ];    // after involution1 + BN + hswish
__device__ float g_ah[NB * CIN * 96];     // sigmoid attention (h)
__device__ float g_aw[NB * CIN * 96];     // sigmoid attention (w)

// ---------------- helpers ----------------
__device__ __forceinline__ void cp_async4(void* smem_dst, const void* gmem_src) {
    unsigned s = (unsigned)__cvta_generic_to_shared(smem_dst);
    asm volatile("cp.async.ca.shared.global [%0], [%1], 4;" :: "r"(s), "l"(gmem_src));
}
__device__ __forceinline__ void cp_commit() {
    asm volatile("cp.async.commit_group;");
}
__device__ __forceinline__ void cp_wait0() {
    asm volatile("cp.async.wait_group 0;" ::: "memory");
}
__device__ __forceinline__ void cp_wait1() {
    asm volatile("cp.async.wait_group 1;" ::: "memory");
}
__device__ __forceinline__ unsigned long long pack2(float a, float b) {
    unsigned long long r;
    asm("mov.b64 %0, {%1, %2};" : "=l"(r) : "f"(a), "f"(b));
    return r;
}
__device__ __forceinline__ unsigned long long ffma2(unsigned long long a,
                                                    unsigned long long b,
                                                    unsigned long long c) {
    unsigned long long d;
    asm("fma.rn.f32x2 %0, %1, %2, %3;" : "=l"(d) : "l"(a), "l"(b), "l"(c));
    return d;
}
__device__ __forceinline__ void unpack2(unsigned long long v, float& lo, float& hi) {
    asm("mov.b64 {%0, %1}, %2;" : "=f"(lo), "=f"(hi) : "l"(v));
}

// ===================== K1: row & col means per (b,c) plane =====================
__global__ void k_means(const float* __restrict__ x) {
    __shared__ float4 sp4[96 * 25];     // row stride 25 float4 (pad)
    const int bc  = blockIdx.x;
    const int tid = threadIdx.x;
    const float4* xp = (const float4*)(x + (size_t)bc * 9216);

    float4 v[9];
    #pragma unroll
    for (int k = 0; k < 9; k++) v[k] = __ldg(&xp[tid + k * 256]);
    #pragma unroll
    for (int k = 0; k < 9; k++) {
        int i = tid + k * 256;
        int r = i / 24, c4 = i % 24;
        sp4[r * 25 + c4] = v[k];
    }
    __syncthreads();

    if (tid < 96) {
        const float4* rp = &sp4[tid * 25];
        float4 a = make_float4(0.f, 0.f, 0.f, 0.f);
        #pragma unroll 6
        for (int j = 0; j < 24; j++) {
            float4 q = rp[j];
            a.x += q.x; a.y += q.y; a.z += q.z; a.w += q.w;
        }
        float s = (a.x + a.y) + (a.z + a.w);
        g_y0[(size_t)bc * SEQ + tid] = s * (1.f / 96.f);
    } else if (tid < 192) {
        int c = tid - 96;
        const float* spf = (const float*)sp4;    // row stride 100 floats
        float s0 = 0.f, s1 = 0.f, s2 = 0.f, s3 = 0.f;
        #pragma unroll 8
        for (int r = 0; r < 96; r += 4) {
            s0 += spf[(r + 0) * 100 + c];
            s1 += spf[(r + 1) * 100 + c];
            s2 += spf[(r + 2) * 100 + c];
            s3 += spf[(r + 3) * 100 + c];
        }
        g_y0[(size_t)bc * SEQ + 96 + c] = ((s0 + s1) + (s2 + s3)) * (1.f / 96.f);
    }
}

// ========== K2: fused conv1x1(256->64) + involution(192) + BN + hswish ==========
#define C1_SMEM_FLOATS 32756
__global__ void __launch_bounds__(512, 1)
k_cinv1(const float* __restrict__ wc1, const float* __restrict__ bc1,
        const float* __restrict__ w1, const float* __restrict__ b1,
        const float* __restrict__ w2, const float* __restrict__ b2,
        const float* __restrict__ bng, const float* __restrict__ bnb,
        const float* __restrict__ bnm, const float* __restrict__ bnv) {
    extern __shared__ float dyn[];
    float* sw1  = dyn;                 // 16448 (64 x pad257)
    float* sww1 = sw1  + 16448;        // 1024
    float* sb1  = sww1 + 1024;         // 16
    float* sw2  = sb1  + 16;           // 3136
    float* sb2  = sw2  + 3136;         // 196
    float* sbc1 = sb2  + 196;          // 64
    float* sbn  = sbc1 + 64;           // 256
    float* ys   = sbn  + 256;          // 8192 (256 x 32)
    float* y1s  = ys   + 8192;         // 2368 (64 x pad37)
    float* st   = y1s  + 2368;         // 384
    float* sg   = st   + 384;          // 672

    const int b   = blockIdx.x >> 3;
    const int p0  = (blockIdx.x & 7) * 24;
    const int tid = threadIdx.x;

    for (int i = tid; i < 64 * 256; i += 512)
        cp_async4(&sw1[(i >> 8) * 257 + (i & 255)], wc1 + i);
    for (int i = tid; i < 1024; i += 512) cp_async4(&sww1[i], w1 + i);
    if (tid < 16)  cp_async4(&sb1[tid], b1 + tid);
    for (int i = tid; i < 3136; i += 512) cp_async4(&sw2[i], w2 + i);
    if (tid < 196) cp_async4(&sb2[tid], b2 + tid);
    if (tid < 64)  cp_async4(&sbc1[tid], bc1 + tid);
    if (tid < 64)        cp_async4(&sbn[tid], bng + tid);
    else if (tid < 128)  cp_async4(&sbn[tid], bnb + tid - 64);
    else if (tid < 192)  cp_async4(&sbn[tid], bnm + tid - 128);
    else if (tid < 256)  cp_async4(&sbn[tid], bnv + tid - 192);
    cp_commit();

    for (int i = tid; i < CIN * 32; i += 512) {
        int c = i >> 5, ps = i & 31;
        int gp = p0 - 3 + ps;
        ys[i] = (gp >= 0 && gp < SEQ) ? g_y0[((size_t)b * CIN + c) * SEQ + gp] : 0.f;
    }
    cp_wait0();
    __syncthreads();

    // conv1x1 (packed f32x2): y1[o][ps], 64 o x 32 ps, all 512 threads
    {
        const int o  = tid & 63;
        const int pg = tid >> 6;
        unsigned long long a0 = 0ull, a1 = 0ull;
        #pragma unroll 8
        for (int c = 0; c < CIN; c++) {
            float wv = sw1[o * 257 + c];
            unsigned long long wp = pack2(wv, wv);
            longlong2 y = *(const longlong2*)&ys[c * 32 + pg * 4];
            a0 = ffma2(wp, (unsigned long long)y.x, a0);
            a1 = ffma2(wp, (unsigned long long)y.y, a1);
        }
        float v0, v1, v2, v3;
        unpack2(a0, v0, v1); unpack2(a1, v2, v3);
        float bo = sbc1[o];
        float* dst = &y1s[o * 37 + pg * 4];
        int gbase = p0 - 3 + pg * 4;
        dst[0] = (gbase + 0 >= 0 && gbase + 0 < SEQ) ? v0 + bo : 0.f;
        dst[1] = (gbase + 1 >= 0 && gbase + 1 < SEQ) ? v1 + bo : 0.f;
        dst[2] = (gbase + 2 >= 0 && gbase + 2 < SEQ) ? v2 + bo : 0.f;
        dst[3] = (gbase + 3 >= 0 && gbase + 3 < SEQ) ? v3 + bo : 0.f;
    }
    __syncthreads();

    if (tid < 384) {
        int r = tid / 24, p = tid % 24;
        float acc = sb1[r];
        const float* wr = &sww1[r * 64];
        #pragma unroll 8
        for (int c = 0; c < MIP; c++) acc += wr[c] * y1s[c * 37 + 3 + p];
        st[r * 24 + p] = acc;
    }
    __syncthreads();

    for (int i = tid; i < 28 * 24; i += 512) {
        int r = i / 24, p = i % 24;
        int g = r / 7, kh = r % 7;
        int row = g * 49 + kh * 7 + 3;
        float acc = sb2[row];
        const float* wr = &sw2[row * 16];
        #pragma unroll
        for (int c = 0; c < 16; c++) acc += wr[c] * st[c * 24 + p];
        sg[i] = acc;
    }
    __syncthreads();

    for (int i = tid; i < MIP * 24; i += 512) {
        int c = i / 24, p = i % 24;
        int g = c >> 4;
        float acc = 0.f;
        #pragma unroll
        for (int kh = 0; kh < 7; kh++)
            acc += sg[(g * 7 + kh) * 24 + p] * y1s[c * 37 + p + kh];
        float sc = sbn[c] * rsqrtf(sbn[192 + c] + 1e-5f);
        float v  = (acc - sbn[128 + c]) * sc + sbn[64 + c];
        float hs = v * fminf(fmaxf(v + 3.f, 0.f), 6.f) * (1.f / 6.f);
        g_y2[((size_t)b * MIP + c) * SEQ + p0 + p] = hs;
    }
}

// ========== K3: involution (96-seq, h/w half) + conv1x1 64->256 + sigmoid ==========
#define C2_SMEM_FLOATS 25908
__global__ void __launch_bounds__(512, 2)
k_inv2(const float* __restrict__ w1h, const float* __restrict__ b1h,
       const float* __restrict__ w2h, const float* __restrict__ b2h,
       const float* __restrict__ wch, const float* __restrict__ bch,
       const float* __restrict__ w1w, const float* __restrict__ b1w,
       const float* __restrict__ w2w, const float* __restrict__ b2w,
       const float* __restrict__ wcw, const float* __restrict__ bcw) {
    extern __shared__ float dyn[];
    float* sw   = dyn;               // 16640 (256 x pad65)
    float* sww1 = sw   + 16640;      // 1024
    float* sb1  = sww1 + 1024;       // 16
    float* sw2  = sb1  + 16;         // 3136
    float* sb2  = sw2  + 3136;       // 196
    float* sbc  = sb2  + 196;        // 256
    float* sy   = sbc  + 256;        // 2048
    float* st   = sy   + 2048;       // 384
    float* sg   = st   + 384;        // 672
    float* sz   = sg   + 672;        // 1536

    const int bid  = blockIdx.x;
    const int b    = bid >> 3;
    const int rest = bid & 7;
    const int half = rest >> 2;
    const int p0   = (rest & 3) * 24;
    const int tid  = threadIdx.x;

    const float* w1 = half ? w1w : w1h;
    const float* b1 = half ? b1w : b1h;
    const float* w2 = half ? w2w : w2h;
    const float* b2 = half ? b2w : b2h;
    const float* wc = half ? wcw : wch;
    const float* bc = half ? bcw : bch;
    float* outbuf   = half ? g_aw : g_ah;

    for (int i = tid; i < 1024; i += 512) cp_async4(&sww1[i], w1 + i);
    if (tid < 16)  cp_async4(&sb1[tid], b1 + tid);
    for (int i = tid; i < 3136; i += 512) cp_async4(&sw2[i], w2 + i);
    if (tid < 196) cp_async4(&sb2[tid], b2 + tid);
    if (tid < 256) cp_async4(&sbc[tid], bc + tid);
    cp_commit();
    for (int i = tid; i < CIN * MIP; i += 512)
        cp_async4(&sw[(i >> 6) * 65 + (i & 63)], wc + i);
    cp_commit();

    for (int i = tid; i < MIP * 32; i += 512) {
        int c = i >> 5, ps = i & 31;
        int gp = p0 - 3 + ps;
        sy[i] = (gp >= 0 && gp < 96)
              ? g_y2[((size_t)b * MIP + c) * SEQ + half * 96 + gp] : 0.f;
    }
    cp_wait1();
    __syncthreads();

    if (tid < 384) {
        int r = tid / 24, p = tid % 24;
        float acc = sb1[r];
        const float* wr = &sww1[r * 64];
        #pragma unroll 8
        for (int c = 0; c < MIP; c++) acc += wr[c] * sy[c * 32 + 3 + p];
        st[r * 24 + p] = acc;
    }
    __syncthreads();

    for (int i = tid; i < 28 * 24; i += 512) {
        int r = i / 24, p = i % 24;
        int g = r / 7, kh = r % 7;
        int row = half ? (g * 49 + 21 + kh) : (g * 49 + kh * 7 + 3);
        float acc = sb2[row];
        const float* wr = &sw2[row * 16];
        #pragma unroll
        for (int c = 0; c < 16; c++) acc += wr[c] * st[c * 24 + p];
        sg[i] = acc;
    }
    __syncthreads();

    for (int i = tid; i < MIP * 24; i += 512) {
        int c = i / 24, p = i % 24;
        int g = c >> 4;
        float acc = 0.f;
        #pragma unroll
        for (int kh = 0; kh < 7; kh++)
            acc += sg[(g * 7 + kh) * 24 + p] * sy[c * 32 + p + kh];
        sz[c * 24 + p] = acc;
    }
    cp_wait0();
    __syncthreads();

    // conv 64 -> 256 + sigmoid (packed f32x2); all 512 threads: (og, q), 12 pos
    {
        const int og = tid >> 1;
        const int q  = tid & 1;
        unsigned long long acc[6];
        #pragma unroll
        for (int k = 0; k < 6; k++) acc[k] = 0ull;
        #pragma unroll 4
        for (int c = 0; c < MIP; c++) {
            float wv = sw[og * 65 + c];
            unsigned long long wp = pack2(wv, wv);
            const longlong2* zp = (const longlong2*)&sz[c * 24 + q * 12];
            longlong2 za = zp[0];
            longlong2 zb = zp[1];
            longlong2 zc = zp[2];
            acc[0] = ffma2(wp, (unsigned long long)za.x, acc[0]);
            acc[1] = ffma2(wp, (unsigned long long)za.y, acc[1]);
            acc[2] = ffma2(wp, (unsigned long long)zb.x, acc[2]);
            acc[3] = ffma2(wp, (unsigned long long)zb.y, acc[3]);
            acc[4] = ffma2(wp, (unsigned long long)zc.x, acc[4]);
            acc[5] = ffma2(wp, (unsigned long long)zc.y, acc[5]);
        }
        float bo = sbc[og];
        float* op = outbuf + ((size_t)b * CIN + og) * 96 + p0 + q * 12;
        #pragma unroll
        for (int k = 0; k < 6; k++) {
            float lo, hi;
            unpack2(acc[k], lo, hi);
            op[2 * k]     = 1.f / (1.f + __expf(-(lo + bo)));
            op[2 * k + 1] = 1.f / (1.f + __expf(-(hi + bo)));
        }
    }
}

// ===================== K4: out = x * a_h * a_w, 4 float4 per thread =====================
// Reversed traversal + streaming stores (cross-replay L2 reuse for k_means).
// grid = (3, NB*CIN), block = 192; quad index t4 in [0,576), elems 4*t4 .. 4*t4+3
__global__ void k_final(const float4* __restrict__ x, float4* __restrict__ out) {
    int bc    = 4095 - (int)blockIdx.y;
    int chunk = 2 - (int)blockIdx.x;
    int t4  = chunk * 192 + threadIdx.x;
    int row = t4 / 6;
    int jf  = (t4 % 6) * 4;

    float h = __ldg(g_ah + (size_t)bc * 96 + row);
    const float4* aw4 = (const float4*)g_aw;
    float4 w0 = __ldg(aw4 + (size_t)bc * 24 + jf);
    float4 w1 = __ldg(aw4 + (size_t)bc * 24 + jf + 1);
    float4 w2 = __ldg(aw4 + (size_t)bc * 24 + jf + 2);
    float4 w3 = __ldg(aw4 + (size_t)bc * 24 + jf + 3);

    size_t idx = (size_t)bc * 2304 + 4 * t4;
    float4 x0 = __ldg(x + idx);
    float4 x1 = __ldg(x + idx + 1);
    float4 x2 = __ldg(x + idx + 2);
    float4 x3 = __ldg(x + idx + 3);

    float4 r0, r1, r2, r3;
    r0.x = x0.x * h * w0.x; r0.y = x0.y * h * w0.y;
    r0.z = x0.z * h * w0.z; r0.w = x0.w * h * w0.w;
    r1.x = x1.x * h * w1.x; r1.y = x1.y * h * w1.y;
    r1.z = x1.z * h * w1.z; r1.w = x1.w * h * w1.w;
    r2.x = x2.x * h * w2.x; r2.y = x2.y * h * w2.y;
    r2.z = x2.z * h * w2.z; r2.w = x2.w * h * w2.w;
    r3.x = x3.x * h * w3.x; r3.y = x3.y * h * w3.y;
    r3.z = x3.z * h * w3.z; r3.w = x3.w * h * w3.w;
    __stcs(out + idx,     r0);
    __stcs(out + idx + 1, r1);
    __stcs(out + idx + 2, r2);
    __stcs(out + idx + 3, r3);
}

// ===================== launch =====================
extern "C" void kernel_launch(void* const* d_in, const int* in_sizes, int n_in,
                              void* d_out, int out_size) {
    const float* x     = (const float*)d_in[0];
    const float* w_c1  = (const float*)d_in[1];
    const float* b_c1  = (const float*)d_in[2];
    const float* i1w1  = (const float*)d_in[3];
    const float* i1b1  = (const float*)d_in[4];
    const float* i1w2  = (const float*)d_in[5];
    const float* i1b2  = (const float*)d_in[6];
    const float* bng   = (const float*)d_in[7];
    const float* bnb   = (const float*)d_in[8];
    const float* bnm   = (const float*)d_in[9];
    const float* bnv   = (const float*)d_in[10];
    const float* ihw1  = (const float*)d_in[11];
    const float* ihb1  = (const float*)d_in[12];
    const float* ihw2  = (const float*)d_in[13];
    const float* ihb2  = (const float*)d_in[14];
    const float* w_h   = (const float*)d_in[15];
    const float* b_h   = (const float*)d_in[16];
    const float* iww1  = (const float*)d_in[17];
    const float* iwb1  = (const float*)d_in[18];
    const float* iww2  = (const float*)d_in[19];
    const float* iwb2  = (const float*)d_in[20];
    const float* w_w   = (const float*)d_in[21];
    const float* b_w   = (const float*)d_in[22];

    cudaFuncSetAttribute(k_cinv1, cudaFuncAttributeMaxDynamicSharedMemorySize,
                         C1_SMEM_FLOATS * 4);
    cudaFuncSetAttribute(k_inv2, cudaFuncAttributeMaxDynamicSharedMemorySize,
                         C2_SMEM_FLOATS * 4);

    k_means<<<NB * CIN, 256>>>(x);
    k_cinv1<<<NB * 8, 512, C1_SMEM_FLOATS * 4>>>(w_c1, b_c1, i1w1, i1b1, i1w2, i1b2,
                                                 bng, bnb, bnm, bnv);
    k_inv2<<<NB * 2 * 4, 512, C2_SMEM_FLOATS * 4>>>(ihw1, ihb1, ihw2, ihb2, w_h, b_h,
                                                    iww1, iwb1, iww2, iwb2, w_w, b_w);
    k_final<<<dim3(3, NB * CIN), 192>>>((const float4*)x, (float4*)d_out);
}

// round 8
// speedup vs baseline: 1.1662x; 1.1662x over previous
#include <cuda_runtime.h>
#include <math.h>

#define NB   16
#define CIN  256
#define MIP  64
#define SEQ  192

// ---- scratch (device globals; no allocation allowed) ----
__device__ float g_y0[NB * CIN * SEQ];    // pooled + concat (b, 256, 192)
__device__ float g_y2[NB * MIP * SEQ];    // after involution1 + BN + hswish
__device__ float g_ah[NB * CIN * 96];     // sigmoid attention (h)
__device__ float g_aw[NB * CIN * 96];     // sigmoid attention (w)

// ---------------- helpers ----------------
__device__ __forceinline__ void cp_async4(void* smem_dst, const void* gmem_src) {
    unsigned s = (unsigned)__cvta_generic_to_shared(smem_dst);
    asm volatile("cp.async.ca.shared.global [%0], [%1], 4;" :: "r"(s), "l"(gmem_src));
}
__device__ __forceinline__ void cp_commit() {
    asm volatile("cp.async.commit_group;");
}
__device__ __forceinline__ void cp_wait0() {
    asm volatile("cp.async.wait_group 0;" ::: "memory");
}
__device__ __forceinline__ void cp_wait1() {
    asm volatile("cp.async.wait_group 1;" ::: "memory");
}
__device__ __forceinline__ unsigned long long pack2(float a, float b) {
    unsigned long long r;
    asm("mov.b64 %0, {%1, %2};" : "=l"(r) : "f"(a), "f"(b));
    return r;
}
__device__ __forceinline__ unsigned long long ffma2(unsigned long long a,
                                                    unsigned long long b,
                                                    unsigned long long c) {
    unsigned long long d;
    asm("fma.rn.f32x2 %0, %1, %2, %3;" : "=l"(d) : "l"(a), "l"(b), "l"(c));
    return d;
}
__device__ __forceinline__ void unpack2(unsigned long long v, float& lo, float& hi) {
    asm("mov.b64 {%0, %1}, %2;" : "=f"(lo), "=f"(hi) : "l"(v));
}

// ===================== K1: row & col means per (b,c) plane =====================
// block = 288 (9 warps). Thread (c4 = tid%24, rg = tid/24) loads 8 float4 of
// column-block c4 over rows [8rg, 8rg+8): column partials accumulate in
// registers; only per-row 4-sums + 12x24 col partials go through smem (14.2KB).
__global__ void k_means(const float* __restrict__ x) {
    __shared__ float  srp[96 * 25];       // per-(row, c4) 4-sums, pad 25
    __shared__ float4 sc4[12 * 24];       // per-(rg, c4) column partials
    const int bc  = blockIdx.x;
    const int tid = threadIdx.x;
    const int c4  = tid % 24;
    const int rg  = tid / 24;
    const float4* xp = (const float4*)(x + (size_t)bc * 9216);

    float4 v[8];
    #pragma unroll
    for (int j = 0; j < 8; j++) v[j] = __ldg(&xp[(8 * rg + j) * 24 + c4]);

    float4 ca = make_float4(0.f, 0.f, 0.f, 0.f);
    #pragma unroll
    for (int j = 0; j < 8; j++) {
        ca.x += v[j].x; ca.y += v[j].y; ca.z += v[j].z; ca.w += v[j].w;
        srp[(8 * rg + j) * 25 + c4] = (v[j].x + v[j].y) + (v[j].z + v[j].w);
    }
    sc4[rg * 24 + c4] = ca;
    __syncthreads();

    if (tid < 96) {                        // row mean -> position tid
        const float* rp = &srp[tid * 25];
        float s0 = 0.f, s1 = 0.f, s2 = 0.f, s3 = 0.f;
        #pragma unroll
        for (int j = 0; j < 24; j += 4) {
            s0 += rp[j]; s1 += rp[j + 1]; s2 += rp[j + 2]; s3 += rp[j + 3];
        }
        g_y0[(size_t)bc * SEQ + tid] = ((s0 + s1) + (s2 + s3)) * (1.f / 96.f);
    } else if (tid < 192) {                // col mean -> position 96 + c
        int c = tid - 96;
        const float* scf = (const float*)sc4;     // [rg*96 + c]
        float s0 = 0.f, s1 = 0.f, s2 = 0.f, s3 = 0.f;
        #pragma unroll
        for (int r = 0; r < 12; r += 4) {
            s0 += scf[(r + 0) * 96 + c];
            s1 += scf[(r + 1) * 96 + c];
            s2 += scf[(r + 2) * 96 + c];
            s3 += scf[(r + 3) * 96 + c];
        }
        g_y0[(size_t)bc * SEQ + 96 + c] = ((s0 + s1) + (s2 + s3)) * (1.f / 96.f);
    }
}

// ========== K2: fused conv1x1(256->64) + involution(192) + BN + hswish ==========
#define C1_SMEM_FLOATS 32756
__global__ void __launch_bounds__(512, 1)
k_cinv1(const float* __restrict__ wc1, const float* __restrict__ bc1,
        const float* __restrict__ w1, const float* __restrict__ b1,
        const float* __restrict__ w2, const float* __restrict__ b2,
        const float* __restrict__ bng, const float* __restrict__ bnb,
        const float* __restrict__ bnm, const float* __restrict__ bnv) {
    extern __shared__ float dyn[];
    float* sw1  = dyn;                 // 16448 (64 x pad257)
    float* sww1 = sw1  + 16448;        // 1024
    float* sb1  = sww1 + 1024;         // 16
    float* sw2  = sb1  + 16;           // 3136
    float* sb2  = sw2  + 3136;         // 196
    float* sbc1 = sb2  + 196;          // 64
    float* sbn  = sbc1 + 64;           // 256
    float* ys   = sbn  + 256;          // 8192 (256 x 32)
    float* y1s  = ys   + 8192;         // 2368 (64 x pad37)
    float* st   = y1s  + 2368;         // 384
    float* sg   = st   + 384;          // 672

    const int b   = blockIdx.x >> 3;
    const int p0  = (blockIdx.x & 7) * 24;
    const int tid = threadIdx.x;

    for (int i = tid; i < 64 * 256; i += 512)
        cp_async4(&sw1[(i >> 8) * 257 + (i & 255)], wc1 + i);
    for (int i = tid; i < 1024; i += 512) cp_async4(&sww1[i], w1 + i);
    if (tid < 16)  cp_async4(&sb1[tid], b1 + tid);
    for (int i = tid; i < 3136; i += 512) cp_async4(&sw2[i], w2 + i);
    if (tid < 196) cp_async4(&sb2[tid], b2 + tid);
    if (tid < 64)  cp_async4(&sbc1[tid], bc1 + tid);
    if (tid < 64)        cp_async4(&sbn[tid], bng + tid);
    else if (tid < 128)  cp_async4(&sbn[tid], bnb + tid - 64);
    else if (tid < 192)  cp_async4(&sbn[tid], bnm + tid - 128);
    else if (tid < 256)  cp_async4(&sbn[tid], bnv + tid - 192);
    cp_commit();

    for (int i = tid; i < CIN * 32; i += 512) {
        int c = i >> 5, ps = i & 31;
        int gp = p0 - 3 + ps;
        ys[i] = (gp >= 0 && gp < SEQ) ? g_y0[((size_t)b * CIN + c) * SEQ + gp] : 0.f;
    }
    cp_wait0();
    __syncthreads();

    // conv1x1 (packed f32x2): y1[o][ps], 64 o x 32 ps, all 512 threads
    {
        const int o  = tid & 63;
        const int pg = tid >> 6;
        unsigned long long a0 = 0ull, a1 = 0ull;
        #pragma unroll 8
        for (int c = 0; c < CIN; c++) {
            float wv = sw1[o * 257 + c];
            unsigned long long wp = pack2(wv, wv);
            longlong2 y = *(const longlong2*)&ys[c * 32 + pg * 4];
            a0 = ffma2(wp, (unsigned long long)y.x, a0);
            a1 = ffma2(wp, (unsigned long long)y.y, a1);
        }
        float v0, v1, v2, v3;
        unpack2(a0, v0, v1); unpack2(a1, v2, v3);
        float bo = sbc1[o];
        float* dst = &y1s[o * 37 + pg * 4];
        int gbase = p0 - 3 + pg * 4;
        dst[0] = (gbase + 0 >= 0 && gbase + 0 < SEQ) ? v0 + bo : 0.f;
        dst[1] = (gbase + 1 >= 0 && gbase + 1 < SEQ) ? v1 + bo : 0.f;
        dst[2] = (gbase + 2 >= 0 && gbase + 2 < SEQ) ? v2 + bo : 0.f;
        dst[3] = (gbase + 3 >= 0 && gbase + 3 < SEQ) ? v3 + bo : 0.f;
    }
    __syncthreads();

    if (tid < 384) {
        int r = tid / 24, p = tid % 24;
        float acc = sb1[r];
        const float* wr = &sww1[r * 64];
        #pragma unroll 8
        for (int c = 0; c < MIP; c++) acc += wr[c] * y1s[c * 37 + 3 + p];
        st[r * 24 + p] = acc;
    }
    __syncthreads();

    for (int i = tid; i < 28 * 24; i += 512) {
        int r = i / 24, p = i % 24;
        int g = r / 7, kh = r % 7;
        int row = g * 49 + kh * 7 + 3;
        float acc = sb2[row];
        const float* wr = &sw2[row * 16];
        #pragma unroll
        for (int c = 0; c < 16; c++) acc += wr[c] * st[c * 24 + p];
        sg[i] = acc;
    }
    __syncthreads();

    for (int i = tid; i < MIP * 24; i += 512) {
        int c = i / 24, p = i % 24;
        int g = c >> 4;
        float acc = 0.f;
        #pragma unroll
        for (int kh = 0; kh < 7; kh++)
            acc += sg[(g * 7 + kh) * 24 + p] * y1s[c * 37 + p + kh];
        float sc = sbn[c] * rsqrtf(sbn[192 + c] + 1e-5f);
        float v  = (acc - sbn[128 + c]) * sc + sbn[64 + c];
        float hs = v * fminf(fmaxf(v + 3.f, 0.f), 6.f) * (1.f / 6.f);
        g_y2[((size_t)b * MIP + c) * SEQ + p0 + p] = hs;
    }
}

// ========== K3: involution (96-seq, h/w half) + conv1x1 64->256 + sigmoid ==========
#define C2_SMEM_FLOATS 25908
__global__ void __launch_bounds__(512, 2)
k_inv2(const float* __restrict__ w1h, const float* __restrict__ b1h,
       const float* __restrict__ w2h, const float* __restrict__ b2h,
       const float* __restrict__ wch, const float* __restrict__ bch,
       const float* __restrict__ w1w, const float* __restrict__ b1w,
       const float* __restrict__ w2w, const float* __restrict__ b2w,
       const float* __restrict__ wcw, const float* __restrict__ bcw) {
    extern __shared__ float dyn[];
    float* sw   = dyn;               // 16640 (256 x pad65)
    float* sww1 = sw   + 16640;      // 1024
    float* sb1  = sww1 + 1024;       // 16
    float* sw2  = sb1  + 16;         // 3136
    float* sb2  = sw2  + 3136;       // 196
    float* sbc  = sb2  + 196;        // 256
    float* sy   = sbc  + 256;        // 2048
    float* st   = sy   + 2048;       // 384
    float* sg   = st   + 384;        // 672
    float* sz   = sg   + 672;        // 1536

    const int bid  = blockIdx.x;
    const int b    = bid >> 3;
    const int rest = bid & 7;
    const int half = rest >> 2;
    const int p0   = (rest & 3) * 24;
    const int tid  = threadIdx.x;

    const float* w1 = half ? w1w : w1h;
    const float* b1 = half ? b1w : b1h;
    const float* w2 = half ? w2w : w2h;
    const float* b2 = half ? b2w : b2h;
    const float* wc = half ? wcw : wch;
    const float* bc = half ? bcw : bch;
    float* outbuf   = half ? g_aw : g_ah;

    for (int i = tid; i < 1024; i += 512) cp_async4(&sww1[i], w1 + i);
    if (tid < 16)  cp_async4(&sb1[tid], b1 + tid);
    for (int i = tid; i < 3136; i += 512) cp_async4(&sw2[i], w2 + i);
    if (tid < 196) cp_async4(&sb2[tid], b2 + tid);
    if (tid < 256) cp_async4(&sbc[tid], bc + tid);
    cp_commit();
    for (int i = tid; i < CIN * MIP; i += 512)
        cp_async4(&sw[(i >> 6) * 65 + (i & 63)], wc + i);
    cp_commit();

    for (int i = tid; i < MIP * 32; i += 512) {
        int c = i >> 5, ps = i & 31;
        int gp = p0 - 3 + ps;
        sy[i] = (gp >= 0 && gp < 96)
              ? g_y2[((size_t)b * MIP + c) * SEQ + half * 96 + gp] : 0.f;
    }
    cp_wait1();
    __syncthreads();

    if (tid < 384) {
        int r = tid / 24, p = tid % 24;
        float acc = sb1[r];
        const float* wr = &sww1[r * 64];
        #pragma unroll 8
        for (int c = 0; c < MIP; c++) acc += wr[c] * sy[c * 32 + 3 + p];
        st[r * 24 + p] = acc;
    }
    __syncthreads();

    for (int i = tid; i < 28 * 24; i += 512) {
        int r = i / 24, p = i % 24;
        int g = r / 7, kh = r % 7;
        int row = half ? (g * 49 + 21 + kh) : (g * 49 + kh * 7 + 3);
        float acc = sb2[row];
        const float* wr = &sw2[row * 16];
        #pragma unroll
        for (int c = 0; c < 16; c++) acc += wr[c] * st[c * 24 + p];
        sg[i] = acc;
    }
    __syncthreads();

    for (int i = tid; i < MIP * 24; i += 512) {
        int c = i / 24, p = i % 24;
        int g = c >> 4;
        float acc = 0.f;
        #pragma unroll
        for (int kh = 0; kh < 7; kh++)
            acc += sg[(g * 7 + kh) * 24 + p] * sy[c * 32 + p + kh];
        sz[c * 24 + p] = acc;
    }
    cp_wait0();
    __syncthreads();

    // conv 64 -> 256 + sigmoid (packed f32x2); all 512 threads: (og, q), 12 pos
    {
        const int og = tid >> 1;
        const int q  = tid & 1;
        unsigned long long acc[6];
        #pragma unroll
        for (int k = 0; k < 6; k++) acc[k] = 0ull;
        #pragma unroll 4
        for (int c = 0; c < MIP; c++) {
            float wv = sw[og * 65 + c];
            unsigned long long wp = pack2(wv, wv);
            const longlong2* zp = (const longlong2*)&sz[c * 24 + q * 12];
            longlong2 za = zp[0];
            longlong2 zb = zp[1];
            longlong2 zc = zp[2];
            acc[0] = ffma2(wp, (unsigned long long)za.x, acc[0]);
            acc[1] = ffma2(wp, (unsigned long long)za.y, acc[1]);
            acc[2] = ffma2(wp, (unsigned long long)zb.x, acc[2]);
            acc[3] = ffma2(wp, (unsigned long long)zb.y, acc[3]);
            acc[4] = ffma2(wp, (unsigned long long)zc.x, acc[4]);
            acc[5] = ffma2(wp, (unsigned long long)zc.y, acc[5]);
        }
        float bo = sbc[og];
        float* op = outbuf + ((size_t)b * CIN + og) * 96 + p0 + q * 12;
        #pragma unroll
        for (int k = 0; k < 6; k++) {
            float lo, hi;
            unpack2(acc[k], lo, hi);
            op[2 * k]     = 1.f / (1.f + __expf(-(lo + bo)));
            op[2 * k + 1] = 1.f / (1.f + __expf(-(hi + bo)));
        }
    }
}

// ===================== K4: out = x * a_h * a_w, 2 float4 per thread =====================
// Reversed traversal + streaming stores (cross-replay L2 reuse for k_means).
// grid = (6, NB*CIN), block = 192
__global__ void k_final(const float4* __restrict__ x, float4* __restrict__ out) {
    int bc    = 4095 - (int)blockIdx.y;
    int chunk = 5 - (int)blockIdx.x;
    int t2 = chunk * 192 + threadIdx.x;
    int row = t2 / 12;
    int jf  = (t2 % 12) * 2;

    float h = __ldg(g_ah + (size_t)bc * 96 + row);
    const float4* aw4 = (const float4*)g_aw;
    float4 w0 = __ldg(aw4 + (size_t)bc * 24 + jf);
    float4 w1 = __ldg(aw4 + (size_t)bc * 24 + jf + 1);

    size_t idx = (size_t)bc * 2304 + 2 * t2;
    float4 x0 = __ldg(x + idx);
    float4 x1 = __ldg(x + idx + 1);

    float4 r0, r1;
    r0.x = x0.x * h * w0.x; r0.y = x0.y * h * w0.y;
    r0.z = x0.z * h * w0.z; r0.w = x0.w * h * w0.w;
    r1.x = x1.x * h * w1.x; r1.y = x1.y * h * w1.y;
    r1.z = x1.z * h * w1.z; r1.w = x1.w * h * w1.w;
    __stcs(out + idx,     r0);
    __stcs(out + idx + 1, r1);
}

// ===================== launch =====================
extern "C" void kernel_launch(void* const* d_in, const int* in_sizes, int n_in,
                              void* d_out, int out_size) {
    const float* x     = (const float*)d_in[0];
    const float* w_c1  = (const float*)d_in[1];
    const float* b_c1  = (const float*)d_in[2];
    const float* i1w1  = (const float*)d_in[3];
    const float* i1b1  = (const float*)d_in[4];
    const float* i1w2  = (const float*)d_in[5];
    const float* i1b2  = (const float*)d_in[6];
    const float* bng   = (const float*)d_in[7];
    const float* bnb   = (const float*)d_in[8];
    const float* bnm   = (const float*)d_in[9];
    const float* bnv   = (const float*)d_in[10];
    const float* ihw1  = (const float*)d_in[11];
    const float* ihb1  = (const float*)d_in[12];
    const float* ihw2  = (const float*)d_in[13];
    const float* ihb2  = (const float*)d_in[14];
    const float* w_h   = (const float*)d_in[15];
    const float* b_h   = (const float*)d_in[16];
    const float* iww1  = (const float*)d_in[17];
    const float* iwb1  = (const float*)d_in[18];
    const float* iww2  = (const float*)d_in[19];
    const float* iwb2  = (const float*)d_in[20];
    const float* w_w   = (const float*)d_in[21];
    const float* b_w   = (const float*)d_in[22];

    cudaFuncSetAttribute(k_cinv1, cudaFuncAttributeMaxDynamicSharedMemorySize,
                         C1_SMEM_FLOATS * 4);
    cudaFuncSetAttribute(k_inv2, cudaFuncAttributeMaxDynamicSharedMemorySize,
                         C2_SMEM_FLOATS * 4);

    k_means<<<NB * CIN, 288>>>(x);
    k_cinv1<<<NB * 8, 512, C1_SMEM_FLOATS * 4>>>(w_c1, b_c1, i1w1, i1b1, i1w2, i1b2,
                                                 bng, bnb, bnm, bnv);
    k_inv2<<<NB * 2 * 4, 512, C2_SMEM_FLOATS * 4>>>(ihw1, ihb1, ihw2, ihb2, w_h, b_h,
                                                    iww1, iwb1, iww2, iwb2, w_w, b_w);
    k_final<<<dim3(6, NB * CIN), 192>>>((const float4*)x, (float4*)d_out);
}